// round 1
// baseline (speedup 1.0000x reference)
#include <cuda_runtime.h>
#include <math.h>
#include <stdint.h>

// Problem constants
#define D64   64
#define HH    2
#define HD    128
#define LL    3
#define NN    50000
#define GG    128
#define EE    600000
#define NE_   300000
#define NAUG  (NN + GG)          // 50128
#define M0    (EE + 2 * NN)      // 700000
#define MM    (M0 + NAUG)        // 750128
#define TAILR (MM - EE)          // 150128 (e_p rows + loop rows)

#define CDIV(a, b) (((a) + (b) - 1) / (b))

// ---------------- device scratch (static, no allocs) ----------------
__device__ int    g_src[MM];
__device__ int    g_dst[MM];
__device__ float  g_tail[(size_t)TAILR * D64];     // e_aug rows >= EE
__device__ float  g_ee[(size_t)MM * HD];           // e_aug @ e_w
__device__ float  g_h[NAUG * D64];
__device__ float  g_hn[NAUG * D64];
__device__ float  g_agg[NAUG * D64];
__device__ float  g_cat[NAUG * HD];
__device__ float  g_q[NAUG * HD];
__device__ float  g_k[NAUG * HD];
__device__ float  g_v[NAUG * HD];
__device__ float  g_skip[NAUG * HD];
__device__ float  g_t[NAUG * HD];
__device__ float  g_lh[NAUG * D64];
__device__ float  g_ln2[NAUG * D64];
__device__ float  g_ffh[NAUG * 4 * D64];
__device__ float  g_alpha[MM * HH];
__device__ float  g_expa[MM * HH];
__device__ float  g_mmax[NAUG * HH];
__device__ float  g_ssum[NAUG * HH];
__device__ float  g_loopsum[NAUG * D64];
__device__ float  g_cnt[NAUG];
__device__ float  g_cntn[GG];
__device__ double g_lsum[GG];
__device__ double g_lsumsq[GG];
__device__ float  g_mean[GG];
__device__ float  g_rstd[GG];
__device__ int    g_abatch[NAUG];
__device__ float  g_gsum[GG * D64];

// ---------------- helpers ----------------
__device__ __forceinline__ void atomicMaxF(float* addr, float val) {
    if (val >= 0.f) atomicMax((int*)addr, __float_as_int(val));
    else            atomicMin((unsigned int*)addr, __float_as_uint(val));
}

// ---------------- setup kernels ----------------
__global__ void k_build_edges(const int* __restrict__ ei0, const int* __restrict__ ei1,
                              const int* __restrict__ batch) {
    int m = blockIdx.x * blockDim.x + threadIdx.x;
    if (m >= MM) return;
    int s, d;
    if (m < EE)               { s = ei0[m]; d = ei1[m]; }
    else if (m < EE + NN)     { int i = m - EE;          s = i;             d = batch[i] + NN; }
    else if (m < EE + 2 * NN) { int i = m - EE - NN;     s = batch[i] + NN; d = i; }
    else                      { int i = m - EE - 2 * NN; s = i;             d = i; }
    g_src[m] = s; g_dst[m] = d;
}

__global__ void k_abatch(const int* __restrict__ batch) {
    int i = blockIdx.x * blockDim.x + threadIdx.x;
    if (i >= NAUG) return;
    g_abatch[i] = (i < NN) ? batch[i] : (i - NN);
}

__global__ void k_cntn(const int* __restrict__ batch) {
    int i = blockIdx.x * blockDim.x + threadIdx.x;
    if (i >= NN) return;
    atomicAdd(&g_cntn[batch[i]], 1.f);
}

__global__ void k_init_h(const float* __restrict__ x, const float* __restrict__ cond) {
    int idx = blockIdx.x * blockDim.x + threadIdx.x;
    if (idx >= NAUG * D64) return;
    int r = idx / D64;
    g_h[idx] = (r < NN) ? x[idx] : cond[idx - NN * D64];
}

// incoming-edge stats for loop_attr (over the M0 non-loop edges)
__global__ void k_loop_stats(const float* __restrict__ edge_attr) {
    int gw = (blockIdx.x * blockDim.x + threadIdx.x) >> 5;
    int lane = threadIdx.x & 31;
    if (gw >= M0) return;
    int d = g_dst[gw];
    if (gw < EE) {
        float2 v = ((const float2*)(edge_attr + (size_t)gw * D64))[lane];
        atomicAdd(&g_loopsum[d * D64 + 2 * lane], v.x);
        atomicAdd(&g_loopsum[d * D64 + 2 * lane + 1], v.y);
        if (lane == 0) atomicAdd(&g_cnt[d], 1.f);
    } else {
        if (lane == 0) {
            atomicAdd(&g_loopsum[d * D64], 1.f);  // e_p: only col 0 is 1
            atomicAdd(&g_cnt[d], 1.f);
        }
    }
}

__global__ void k_build_tail() {
    int idx = blockIdx.x * blockDim.x + threadIdx.x;
    if (idx >= TAILR * D64) return;
    int r = idx / D64, d = idx % D64;
    float val;
    if (r < 2 * NN) val = (d == 0) ? 1.f : 0.f;   // e_p rows
    else {
        int i = r - 2 * NN;                        // loop_attr rows
        val = g_loopsum[i * D64 + d] / fmaxf(g_cnt[i], 1.f);
    }
    g_tail[idx] = val;
}

// ---------------- graph layernorm ----------------
__global__ void k_ln_stats(const float* __restrict__ X) {
    int i = blockIdx.x * blockDim.x + threadIdx.x;
    if (i >= NAUG) return;
    const float* row = X + i * D64;
    float s = 0.f, ss = 0.f;
#pragma unroll
    for (int d = 0; d < D64; d++) { float v = row[d]; s += v; ss += v * v; }
    int b = g_abatch[i];
    atomicAdd(&g_lsum[b], (double)s);
    atomicAdd(&g_lsumsq[b], (double)ss);
}

__global__ void k_ln_final() {
    int g = threadIdx.x;
    if (g >= GG) return;
    double norm = (double)fmaxf(g_cntn[g] + 1.f, 1.f) * D64;
    double mean = g_lsum[g] / norm;
    double var  = g_lsumsq[g] / norm - mean * mean;
    g_mean[g] = (float)mean;
    g_rstd[g] = rsqrtf((float)var + 1e-5f);
}

__global__ void k_ln_apply(const float* __restrict__ X, float* __restrict__ Y) {
    int idx = blockIdx.x * blockDim.x + threadIdx.x;
    if (idx >= NAUG * D64) return;
    int b = g_abatch[idx / D64];
    Y[idx] = (X[idx] - g_mean[b]) * g_rstd[b];
}

// ---------------- gen_conv edge pass ----------------
__global__ void k_gen_edge(const float* __restrict__ edge_attr) {
    int gw = (blockIdx.x * blockDim.x + threadIdx.x) >> 5;
    int lane = threadIdx.x & 31;
    if (gw >= MM) return;
    int s = g_src[gw], d = g_dst[gw];
    const float* ea = (gw < EE) ? (edge_attr + (size_t)gw * D64)
                                : (g_tail + (size_t)(gw - EE) * D64);
    float2 e2 = ((const float2*)ea)[lane];
    float2 h2 = ((const float2*)(g_hn + s * D64))[lane];
    float m0 = fmaxf(h2.x + e2.x, 0.f) + 1e-7f;
    float m1 = fmaxf(h2.y + e2.y, 0.f) + 1e-7f;
    atomicAdd(&g_agg[d * D64 + 2 * lane],     m0);
    atomicAdd(&g_agg[d * D64 + 2 * lane + 1], m1);
}

// cat[:, :64] = hn ; agg += hn (GEMM input for gen_w)
__global__ void k_prep_cat() {
    int idx = blockIdx.x * blockDim.x + threadIdx.x;
    if (idx >= NAUG * D64) return;
    int i = idx / D64, d = idx % D64;
    float hv = g_hn[idx];
    g_cat[i * HD + d] = hv;
    g_agg[idx] += hv;
}

// ---------------- attention ----------------
__global__ void k_init_mmax() {
    int i = blockIdx.x * blockDim.x + threadIdx.x;
    if (i >= NAUG * HH) return;
    g_mmax[i] = __int_as_float(0xff800000);  // -inf
}

__global__ void k_alpha() {
    int gw = (blockIdx.x * blockDim.x + threadIdx.x) >> 5;
    int lane = threadIdx.x & 31;
    if (gw >= MM) return;
    int s = g_src[gw], d = g_dst[gw];
    float4 e4 = ((const float4*)(g_ee + (size_t)gw * HD))[lane];
    float4 k4 = ((const float4*)(g_k + (size_t)s * HD))[lane];
    float4 q4 = ((const float4*)(g_q + (size_t)d * HD))[lane];
    float p = q4.x * (k4.x + e4.x) + q4.y * (k4.y + e4.y)
            + q4.z * (k4.z + e4.z) + q4.w * (k4.w + e4.w);
#pragma unroll
    for (int off = 8; off; off >>= 1) p += __shfl_down_sync(0xffffffffu, p, off);
    if ((lane & 15) == 0) {
        int h = lane >> 4;
        float a = p * 0.125f;  // 1/sqrt(64)
        g_alpha[gw * 2 + h] = a;
        atomicMaxF(&g_mmax[d * 2 + h], a);
    }
}

__global__ void k_expsum() {
    int idx = blockIdx.x * blockDim.x + threadIdx.x;
    if (idx >= MM * HH) return;
    int m = idx >> 1, h = idx & 1;
    int d = g_dst[m];
    float a = expf(g_alpha[idx] - g_mmax[d * 2 + h]);
    g_expa[idx] = a;
    atomicAdd(&g_ssum[d * 2 + h], a);
}

__global__ void k_msg() {
    int gw = (blockIdx.x * blockDim.x + threadIdx.x) >> 5;
    int lane = threadIdx.x & 31;
    if (gw >= MM) return;
    int s = g_src[gw], d = g_dst[gw];
    float w0 = g_expa[gw * 2]     / (g_ssum[d * 2]     + 1e-16f);
    float w1 = g_expa[gw * 2 + 1] / (g_ssum[d * 2 + 1] + 1e-16f);
    float4 e4 = ((const float4*)(g_ee + (size_t)gw * HD))[lane];
    float4 v4 = ((const float4*)(g_v + (size_t)s * HD))[lane];
    float ww = (lane < 16) ? w0 : w1;
    int base = d * HD + lane * 4;
    atomicAdd(&g_t[base + 0], (v4.x + e4.x) * ww);
    atomicAdd(&g_t[base + 1], (v4.y + e4.y) * ww);
    atomicAdd(&g_t[base + 2], (v4.z + e4.z) * ww);
    atomicAdd(&g_t[base + 3], (v4.w + e4.w) * ww);
}

__global__ void k_addskip() {
    int idx = blockIdx.x * blockDim.x + threadIdx.x;
    if (idx >= NAUG * HD) return;
    g_t[idx] += g_skip[idx];
}

// ---------------- generic tiled GEMM: C = act(A@W + b) [+= if ACCUM] ----------------
// block = 256 threads, 32 rows per block, k tiled by 32, W tile in smem.
template <int IN, int OUT, int ACT, int ACCUM>
__global__ void k_gemm(const float* __restrict__ A, const float* __restrict__ W,
                       const float* __restrict__ bias, float* __restrict__ C,
                       int ldc, int rows) {
    __shared__ float As[32][33];
    __shared__ float Ws[32][OUT];
    const int tx = threadIdx.x & 31;
    const int ty = threadIdx.x >> 5;   // 0..7
    const int r0 = blockIdx.x * 32;
    constexpr int JN = OUT / 32;
    float acc[4][JN];
#pragma unroll
    for (int i = 0; i < 4; i++)
#pragma unroll
        for (int j = 0; j < JN; j++) acc[i][j] = 0.f;

    for (int k0 = 0; k0 < IN; k0 += 32) {
#pragma unroll
        for (int t = 0; t < 4; t++) {
            int li = threadIdx.x + t * 256;  // 0..1023
            int rr = li >> 5, kk = li & 31;
            int row = r0 + rr;
            As[rr][kk] = (row < rows) ? A[(size_t)row * IN + k0 + kk] : 0.f;
        }
#pragma unroll
        for (int t = 0; t < (32 * OUT) / 256; t++) {
            int li = threadIdx.x + t * 256;
            int kk = li / OUT, oo = li % OUT;
            Ws[kk][oo] = W[(size_t)(k0 + kk) * OUT + oo];
        }
        __syncthreads();
#pragma unroll
        for (int kk = 0; kk < 32; kk++) {
            float a0 = As[ty * 4 + 0][kk];
            float a1 = As[ty * 4 + 1][kk];
            float a2 = As[ty * 4 + 2][kk];
            float a3 = As[ty * 4 + 3][kk];
#pragma unroll
            for (int j = 0; j < JN; j++) {
                float wv = Ws[kk][tx + 32 * j];
                acc[0][j] += a0 * wv;
                acc[1][j] += a1 * wv;
                acc[2][j] += a2 * wv;
                acc[3][j] += a3 * wv;
            }
        }
        __syncthreads();
    }
#pragma unroll
    for (int i = 0; i < 4; i++) {
        int row = r0 + ty * 4 + i;
        if (row >= rows) continue;
#pragma unroll
        for (int j = 0; j < JN; j++) {
            int o = tx + 32 * j;
            float v = acc[i][j] + (bias ? bias[o] : 0.f);
            if (ACT == 1) v = (v > 0.f) ? v : 0.01f * v;
            float* cp = &C[(size_t)row * ldc + o];
            if (ACCUM) *cp += v; else *cp = v;
        }
    }
}

// ---------------- outputs ----------------
__global__ void k_glob_sum(const int* __restrict__ batch) {
    int idx = blockIdx.x * blockDim.x + threadIdx.x;
    if (idx >= NN * D64) return;
    atomicAdd(&g_gsum[batch[idx / D64] * D64 + (idx % D64)], g_h[idx]);
}

__global__ void k_glob_out(float* __restrict__ out) {
    int idx = blockIdx.x * blockDim.x + threadIdx.x;
    if (idx >= GG * D64) return;
    int g = idx / D64, d = idx % D64;
    out[NN * D64 + idx] = g_gsum[idx] / fmaxf(g_cntn[g], 1.f) + g_h[(NN + g) * D64 + d];
}

__global__ void k_ne_out(const int* __restrict__ ne0, const int* __restrict__ ne1,
                         float* __restrict__ out) {
    int idx = blockIdx.x * blockDim.x + threadIdx.x;
    if (idx >= NE_ * D64) return;
    int j = idx / D64, d = idx % D64;
    out[(NN + GG) * D64 + idx] = g_h[ne0[j] * D64 + d] + g_h[ne1[j] * D64 + d];
}

// ---------------- host launcher ----------------
#define GETSYM(ptr, sym) do { void* _p; cudaGetSymbolAddress(&_p, sym); ptr = (decltype(ptr))_p; } while (0)

extern "C" void kernel_launch(void* const* d_in, const int* in_sizes, int n_in,
                              void* d_out, int out_size) {
    const float* x          = (const float*)d_in[0];
    const float* cond       = (const float*)d_in[1];
    const float* edge_attr  = (const float*)d_in[2];
    const int*   edge_index = (const int*)d_in[3];
    const int*   ne_index   = (const int*)d_in[4];
    const int*   batch      = (const int*)d_in[5];
    const float* gen_w  = (const float*)d_in[6];
    const float* gen_b  = (const float*)d_in[7];
    const float* q_w    = (const float*)d_in[8];
    const float* q_b    = (const float*)d_in[9];
    const float* k_w    = (const float*)d_in[10];
    const float* k_b    = (const float*)d_in[11];
    const float* v_w    = (const float*)d_in[12];
    const float* v_b    = (const float*)d_in[13];
    const float* e_w    = (const float*)d_in[14];
    const float* skip_w = (const float*)d_in[15];
    const float* skip_b = (const float*)d_in[16];
    const float* lin_w  = (const float*)d_in[17];
    const float* lin_b  = (const float*)d_in[18];
    const float* ff_w1  = (const float*)d_in[19];
    const float* ff_b1  = (const float*)d_in[20];
    const float* ff_w2  = (const float*)d_in[21];
    const float* ff_b2  = (const float*)d_in[22];
    float* out = (float*)d_out;

    float *ee_p, *tail_p, *h_p, *hn_p, *agg_p, *cat_p, *q_p, *k_p, *v_p, *skip_p, *t_p;
    float *lh_p, *ln2_p, *ffh_p, *loopsum_p, *cnt_p, *cntn_p, *ssum_p, *gsum_p;
    double *lsum_p, *lsumsq_p;
    GETSYM(ee_p, g_ee);       GETSYM(tail_p, g_tail);
    GETSYM(h_p, g_h);         GETSYM(hn_p, g_hn);     GETSYM(agg_p, g_agg);
    GETSYM(cat_p, g_cat);     GETSYM(q_p, g_q);       GETSYM(k_p, g_k);
    GETSYM(v_p, g_v);         GETSYM(skip_p, g_skip); GETSYM(t_p, g_t);
    GETSYM(lh_p, g_lh);       GETSYM(ln2_p, g_ln2);   GETSYM(ffh_p, g_ffh);
    GETSYM(loopsum_p, g_loopsum); GETSYM(cnt_p, g_cnt); GETSYM(cntn_p, g_cntn);
    GETSYM(ssum_p, g_ssum);   GETSYM(gsum_p, g_gsum);
    GETSYM(lsum_p, g_lsum);   GETSYM(lsumsq_p, g_lsumsq);

    const int T = 256;
    cudaStream_t st = 0;

    // ---- setup ----
    cudaMemsetAsync(loopsum_p, 0, sizeof(float) * NAUG * D64, st);
    cudaMemsetAsync(cnt_p,     0, sizeof(float) * NAUG, st);
    cudaMemsetAsync(cntn_p,    0, sizeof(float) * GG, st);
    cudaMemsetAsync(gsum_p,    0, sizeof(float) * GG * D64, st);

    k_build_edges<<<CDIV(MM, T), T, 0, st>>>(edge_index, edge_index + EE, batch);
    k_abatch<<<CDIV(NAUG, T), T, 0, st>>>(batch);
    k_cntn<<<CDIV(NN, T), T, 0, st>>>(batch);
    k_init_h<<<CDIV(NAUG * D64, T), T, 0, st>>>(x, cond);
    k_loop_stats<<<CDIV(M0 * 32, T), T, 0, st>>>(edge_attr);
    k_build_tail<<<CDIV(TAILR * D64, T), T, 0, st>>>();

    // ---- layers ----
    for (int i = 0; i < LL; i++) {
        const float* gw  = gen_w  + (size_t)i * D64 * D64;
        const float* gb  = gen_b  + (size_t)i * D64;
        const float* qw  = q_w    + (size_t)i * HD * HD;
        const float* qb  = q_b    + (size_t)i * HD;
        const float* kw  = k_w    + (size_t)i * HD * HD;
        const float* kb  = k_b    + (size_t)i * HD;
        const float* vw  = v_w    + (size_t)i * HD * HD;
        const float* vb  = v_b    + (size_t)i * HD;
        const float* ew  = e_w    + (size_t)i * D64 * HD;
        const float* sw  = skip_w + (size_t)i * HD * HD;
        const float* sb  = skip_b + (size_t)i * HD;
        const float* lw  = lin_w  + (size_t)i * HD * D64;
        const float* lb  = lin_b  + (size_t)i * D64;
        const float* f1w = ff_w1  + (size_t)i * D64 * 4 * D64;
        const float* f1b = ff_b1  + (size_t)i * 4 * D64;
        const float* f2w = ff_w2  + (size_t)i * 4 * D64 * D64;
        const float* f2b = ff_b2  + (size_t)i * D64;

        // LN1
        cudaMemsetAsync(lsum_p,   0, sizeof(double) * GG, st);
        cudaMemsetAsync(lsumsq_p, 0, sizeof(double) * GG, st);
        k_ln_stats<<<CDIV(NAUG, T), T, 0, st>>>(h_p);
        k_ln_final<<<1, GG, 0, st>>>();
        k_ln_apply<<<CDIV(NAUG * D64, T), T, 0, st>>>(h_p, hn_p);

        // gen_conv
        cudaMemsetAsync(agg_p, 0, sizeof(float) * NAUG * D64, st);
        k_gen_edge<<<CDIV(MM * 32, T), T, 0, st>>>(edge_attr);
        k_prep_cat<<<CDIV(NAUG * D64, T), T, 0, st>>>();
        k_gemm<D64, D64, 0, 0><<<CDIV(NAUG, 32), T, 0, st>>>(agg_p, gw, gb, cat_p + D64, HD, NAUG);

        // q, k, v, skip
        k_gemm<HD, HD, 0, 0><<<CDIV(NAUG, 32), T, 0, st>>>(cat_p, qw, qb, q_p, HD, NAUG);
        k_gemm<HD, HD, 0, 0><<<CDIV(NAUG, 32), T, 0, st>>>(cat_p, kw, kb, k_p, HD, NAUG);
        k_gemm<HD, HD, 0, 0><<<CDIV(NAUG, 32), T, 0, st>>>(cat_p, vw, vb, v_p, HD, NAUG);
        k_gemm<HD, HD, 0, 0><<<CDIV(NAUG, 32), T, 0, st>>>(cat_p, sw, sb, skip_p, HD, NAUG);

        // ee = e_aug @ e_w  (split: edge_attr rows, then tail rows)
        k_gemm<D64, HD, 0, 0><<<CDIV(EE, 32), T, 0, st>>>(edge_attr, ew, nullptr, ee_p, HD, EE);
        k_gemm<D64, HD, 0, 0><<<CDIV(TAILR, 32), T, 0, st>>>(tail_p, ew, nullptr,
                                                             ee_p + (size_t)EE * HD, HD, TAILR);

        // attention softmax over incoming edges
        k_init_mmax<<<CDIV(NAUG * HH, T), T, 0, st>>>();
        cudaMemsetAsync(ssum_p, 0, sizeof(float) * NAUG * HH, st);
        k_alpha<<<CDIV(MM * 32, T), T, 0, st>>>();
        k_expsum<<<CDIV(MM * HH, T), T, 0, st>>>();
        cudaMemsetAsync(t_p, 0, sizeof(float) * NAUG * HD, st);
        k_msg<<<CDIV(MM * 32, T), T, 0, st>>>();
        k_addskip<<<CDIV(NAUG * HD, T), T, 0, st>>>();

        // lin
        k_gemm<HD, D64, 0, 0><<<CDIV(NAUG, 32), T, 0, st>>>(t_p, lw, lb, lh_p, D64, NAUG);

        // LN2
        cudaMemsetAsync(lsum_p,   0, sizeof(double) * GG, st);
        cudaMemsetAsync(lsumsq_p, 0, sizeof(double) * GG, st);
        k_ln_stats<<<CDIV(NAUG, T), T, 0, st>>>(lh_p);
        k_ln_final<<<1, GG, 0, st>>>();
        k_ln_apply<<<CDIV(NAUG * D64, T), T, 0, st>>>(lh_p, ln2_p);

        // FF + residual
        k_gemm<D64, 4 * D64, 1, 0><<<CDIV(NAUG, 32), T, 0, st>>>(ln2_p, f1w, f1b, ffh_p, 4 * D64, NAUG);
        k_gemm<4 * D64, D64, 0, 1><<<CDIV(NAUG, 32), T, 0, st>>>(ffh_p, f2w, f2b, h_p, D64, NAUG);
    }

    // ---- outputs ----
    cudaMemcpyAsync(out, h_p, sizeof(float) * NN * D64, cudaMemcpyDeviceToDevice, st);
    k_glob_sum<<<CDIV(NN * D64, T), T, 0, st>>>(batch);
    k_glob_out<<<CDIV(GG * D64, T), T, 0, st>>>(out);
    k_ne_out<<<CDIV(NE_ * D64, T), T, 0, st>>>(ne_index, ne_index + NE_, out);
}